// round 7
// baseline (speedup 1.0000x reference)
#include <cuda_runtime.h>
#include <cuda_bf16.h>

// B = 8192 rows, T = 4096 features, G = 64 groups.
// Group sizes cycle (32, 64, 96, 64) x 16; all boundaries are multiples of 32,
// so each aligned 32-elem chunk belongs to exactly one group (128 chunks/row).
// Output: d_out[0..B) = Z (fp32), d_out[B..B+B*64) = a (fp32 row-major [B,64]).
//
// R7 = R6 body, 2 rows per CTA as a SEQUENTIAL loop (no prefetch registers):
//   - while warp 0 runs row-0's epilogue, warps 1-7 are past the barrier and
//     already issuing row-1's LDG.128s -> epilogue slot-idle hidden for free
//   - ping-pong chunk_sum, one __syncthreads per row
//   - regs stay ~R6 level (no cross-row register prefetch)

#define T_DIM    4096
#define G_DIM    64
#define NTHREADS 256
#define ROWS     2

__global__ __launch_bounds__(NTHREADS)
void agp_kernel(const float* __restrict__ H,
                const float* __restrict__ score_w,
                const float* __restrict__ score_b,
                float* __restrict__ out, int B)
{
    const int tid = threadIdx.x;
    const int b0  = blockIdx.x * ROWS;

    __shared__ float chunk_sum[2][T_DIM / 32];   // ping-pong, 2 x 128

    #pragma unroll 1
    for (int it = 0; it < ROWS; ++it) {
        const int b = b0 + it;
        const int p = it & 1;

        // --- Phase 1: 4 coalesced LDG.128 per thread, butterfly to chunks ---
        const float4* row4 = reinterpret_cast<const float4*>(H + (size_t)b * T_DIM);
        #pragma unroll
        for (int k = 0; k < 4; ++k) {
            float4 v = row4[tid + NTHREADS * k];
            float s = (v.x + v.y) + (v.z + v.w);
            s += __shfl_xor_sync(0xffffffffu, s, 1);
            s += __shfl_xor_sync(0xffffffffu, s, 2);
            s += __shfl_xor_sync(0xffffffffu, s, 4);
            if ((tid & 7) == 0)
                chunk_sum[p][(tid >> 3) + 32 * k] = s;
        }
        __syncthreads();   // warps 1-7 immediately proceed to next row's loads

        // --- Phase 2: warp 0 does groups -> softmax -> Z for row b ---
        if (tid < 32) {
            const float w    = __ldg(score_w);
            const float bias = __ldg(score_b);

            const int   c_start[4] = {0, 1, 3, 6};
            const int   c_cnt[4]   = {1, 2, 3, 2};
            const float inv_sz[4]  = {1.0f/32.0f, 1.0f/64.0f, 1.0f/96.0f, 1.0f/64.0f};

            float Gm[2], sc[2];
            #pragma unroll
            for (int j = 0; j < 2; ++j) {
                int g    = tid + 32 * j;
                int sub  = g & 3;
                int base = (g >> 2) * 8 + c_start[sub];
                float s = 0.0f;
                #pragma unroll
                for (int c = 0; c < 3; ++c)
                    if (c < c_cnt[sub]) s += chunk_sum[p][base + c];
                Gm[j] = s * inv_sz[sub];
                sc[j] = Gm[j] * w + bias;
            }

            float mx = fmaxf(sc[0], sc[1]);
            #pragma unroll
            for (int d = 16; d > 0; d >>= 1)
                mx = fmaxf(mx, __shfl_xor_sync(0xffffffffu, mx, d));

            float p0 = __expf(sc[0] - mx);
            float p1 = __expf(sc[1] - mx);

            float ssum = p0 + p1;
            float pz   = p0 * Gm[0] + p1 * Gm[1];
            #pragma unroll
            for (int d = 16; d > 0; d >>= 1) {
                ssum += __shfl_xor_sync(0xffffffffu, ssum, d);
                pz   += __shfl_xor_sync(0xffffffffu, pz, d);
            }
            float inv = 1.0f / ssum;

            float* a_out = out + B + (size_t)b * G_DIM;
            a_out[tid]      = p0 * inv;
            a_out[tid + 32] = p1 * inv;
            if (tid == 0) out[b] = pz * inv;   // Z = sum(a*G) = pz / ssum
        }
        // no second barrier: next iteration writes the other buffer, and the
        // barrier of iteration it+1 (reached by warp 0 only after this
        // epilogue completes) protects any later reuse.
    }
}

extern "C" void kernel_launch(void* const* d_in, const int* in_sizes, int n_in,
                              void* d_out, int out_size)
{
    const float* H  = (const float*)d_in[0];   // [B, 4096]
    const float* sw = (const float*)d_in[1];   // [1,1]
    const float* sb = (const float*)d_in[2];   // [1]
    float* out = (float*)d_out;

    int B = in_sizes[0] / T_DIM;               // 8192
    agp_kernel<<<B / ROWS, NTHREADS>>>(H, sw, sb, out, B);
}